// round 2
// baseline (speedup 1.0000x reference)
#include <cuda_runtime.h>
#include <cuda_bf16.h>

#define N_CLASSES 9
#define N_GROUPS  2
#define N_BINS    (N_CLASSES * N_GROUPS)   // 18
#define WARPS_PER_BLOCK 8
#define THREADS_PER_BLOCK (WARPS_PER_BLOCK * 32)

// Global scratch (no allocations allowed). Zero-initialized at load;
// the last block of every launch resets them to zero, so every graph
// replay sees a clean state -> deterministic.
__device__ unsigned int g_counts[N_BINS];
__device__ unsigned int g_ticket;

// Single fused kernel:
//  - per-lane privatized shared histogram (conflict-free, atomic-free hot loop)
//  - block reduce -> 18 global atomics per block
//  - last block (ticket) computes the SPD loss, writes out[0], resets globals
__global__ void __launch_bounds__(THREADS_PER_BLOCK)
spd_loss_kernel(const int* __restrict__ preds,
                const int* __restrict__ attrs,
                float* __restrict__ out,
                int n, int n4, float n_total)
{
    __shared__ unsigned int hist[WARPS_PER_BLOCK][N_BINS * 32];
    __shared__ unsigned int blk[N_BINS];
    __shared__ unsigned int is_last;

    // Zero shared
    for (int i = threadIdx.x; i < WARPS_PER_BLOCK * N_BINS * 32; i += THREADS_PER_BLOCK)
        (&hist[0][0])[i] = 0u;
    if (threadIdx.x < N_BINS) blk[threadIdx.x] = 0u;
    __syncthreads();

    const int warp = threadIdx.x >> 5;
    const int lane = threadIdx.x & 31;
    unsigned int* h = &hist[warp][lane];   // lane-offset base; index by bin*32

    const int4* __restrict__ p4 = (const int4*)preds;
    const int4* __restrict__ a4 = (const int4*)attrs;

    const int tid    = blockIdx.x * THREADS_PER_BLOCK + threadIdx.x;
    const int stride = gridDim.x * THREADS_PER_BLOCK;

    // Unroll x2 with front-batched loads: 4 independent LDG.128 in flight.
    int i = tid;
    for (; i + stride < n4; i += 2 * stride) {
        int4 pa = p4[i];
        int4 aa = a4[i];
        int4 pb = p4[i + stride];
        int4 ab = a4[i + stride];

        h[(pa.x * N_GROUPS + aa.x) * 32] += 1u;
        h[(pa.y * N_GROUPS + aa.y) * 32] += 1u;
        h[(pa.z * N_GROUPS + aa.z) * 32] += 1u;
        h[(pa.w * N_GROUPS + aa.w) * 32] += 1u;
        h[(pb.x * N_GROUPS + ab.x) * 32] += 1u;
        h[(pb.y * N_GROUPS + ab.y) * 32] += 1u;
        h[(pb.z * N_GROUPS + ab.z) * 32] += 1u;
        h[(pb.w * N_GROUPS + ab.w) * 32] += 1u;
    }
    for (; i < n4; i += stride) {
        int4 p = p4[i];
        int4 a = a4[i];
        h[(p.x * N_GROUPS + a.x) * 32] += 1u;
        h[(p.y * N_GROUPS + a.y) * 32] += 1u;
        h[(p.z * N_GROUPS + a.z) * 32] += 1u;
        h[(p.w * N_GROUPS + a.w) * 32] += 1u;
    }

    // Scalar tail (n not multiple of 4) — block 0 only.
    if (blockIdx.x == 0) {
        for (int k = n4 * 4 + threadIdx.x; k < n; k += THREADS_PER_BLOCK) {
            int b = preds[k] * N_GROUPS + attrs[k];
            h[b * 32] += 1u;
        }
    }
    __syncthreads();

    // Reduce 8 warps x 576 counters -> 18 block totals (shared atomics, tiny)
    for (int idx = threadIdx.x; idx < N_BINS * 32; idx += THREADS_PER_BLOCK) {
        unsigned int s = 0;
        #pragma unroll
        for (int w = 0; w < WARPS_PER_BLOCK; w++) s += hist[w][idx];
        atomicAdd(&blk[idx >> 5], s);
    }
    __syncthreads();

    // Single-threaded release chain: thread 0 publishes this block's counts,
    // fences, then takes a ticket. The last ticket holder finalizes.
    if (threadIdx.x == 0) {
        #pragma unroll
        for (int b = 0; b < N_BINS; b++)
            atomicAdd(&g_counts[b], blk[b]);
        __threadfence();
        unsigned int t = atomicAdd(&g_ticket, 1u);
        is_last = (t == gridDim.x - 1) ? 1u : 0u;
    }
    __syncthreads();

    if (is_last && threadIdx.x == 0) {
        __threadfence();  // acquire side
        float c[N_BINS];
        #pragma unroll
        for (int b = 0; b < N_BINS; b++) {
            unsigned int v = atomicAdd(&g_counts[b], 0u);  // coherent L2 read
            c[b] = (float)v;
        }

        float n1 = 0.0f;
        #pragma unroll
        for (int b = 0; b < N_CLASSES; b++) n1 += c[2 * b + 1];
        float n0 = n_total - n1;

        float s = 0.0f;
        #pragma unroll
        for (int b = 0; b < N_CLASSES; b++) {
            float d = c[2 * b] / n0 - c[2 * b + 1] / n1;
            s += d * d;
        }
        out[0] = s;

        // Reset globals for the next (graph-replayed) launch.
        #pragma unroll
        for (int b = 0; b < N_BINS; b++)
            atomicExch(&g_counts[b], 0u);
        __threadfence();
        atomicExch(&g_ticket, 0u);
    }
}

extern "C" void kernel_launch(void* const* d_in, const int* in_sizes, int n_in,
                              void* d_out, int out_size)
{
    const int* preds = (const int*)d_in[0];
    const int* attrs = (const int*)d_in[1];
    float* out = (float*)d_out;
    int n  = in_sizes[0];
    int n4 = n >> 2;

    int blocks = (n4 + THREADS_PER_BLOCK - 1) / THREADS_PER_BLOCK;
    const int max_blocks = 148 * 8;   // full chip at 8 CTAs/SM (2048 thr/SM)
    if (blocks > max_blocks) blocks = max_blocks;
    if (blocks < 1) blocks = 1;

    spd_loss_kernel<<<blocks, THREADS_PER_BLOCK>>>(preds, attrs, out, n, n4, (float)n);
}

// round 3
// speedup vs baseline: 1.1526x; 1.1526x over previous
#include <cuda_runtime.h>
#include <cuda_bf16.h>

#define N_CLASSES 9
#define N_GROUPS  2
#define N_BINS    (N_CLASSES * N_GROUPS)   // 18
#define WARPS_PER_BLOCK 8
#define THREADS_PER_BLOCK (WARPS_PER_BLOCK * 32)

// Global scratch (no allocations allowed). Zero-initialized at load; the last
// block of every launch resets them, so every graph replay sees clean state.
__device__ unsigned int g_counts[N_BINS];
__device__ unsigned int g_ticket;

// One bit-sliced ballot round: counts 32 elements (one per lane) into the
// per-lane bin counter. Lane l (l<18) owns bin (class=l>>1, group=l&1).
// m0..m3 / ginv are precomputed per-lane constants.
__device__ __forceinline__ void ballot_round(int pred, int attr,
                                             unsigned m0, unsigned m1,
                                             unsigned m2, unsigned m3,
                                             unsigned ginv, unsigned& cnt)
{
    unsigned b0 = __ballot_sync(0xFFFFFFFFu, (pred & 1) != 0);
    unsigned b1 = __ballot_sync(0xFFFFFFFFu, (pred & 2) != 0);
    unsigned b2 = __ballot_sync(0xFFFFFFFFu, (pred & 4) != 0);
    unsigned b3 = __ballot_sync(0xFFFFFFFFu, (pred & 8) != 0);
    unsigned am = __ballot_sync(0xFFFFFFFFu, attr != 0);
    unsigned mem = ~(b0 ^ m0) & ~(b1 ^ m1) & ~(b2 ^ m2) & ~(b3 ^ m3) & (am ^ ginv);
    cnt += __popc(mem);
}

__global__ void __launch_bounds__(THREADS_PER_BLOCK)
spd_loss_kernel(const int* __restrict__ preds,
                const int* __restrict__ attrs,
                float* __restrict__ out,
                int n, int n4, float n_total)
{
    __shared__ unsigned int warp_cnt[WARPS_PER_BLOCK][N_BINS];
    __shared__ unsigned int is_last;

    const int warp = threadIdx.x >> 5;
    const int lane = threadIdx.x & 31;

    // Per-lane constants for bit-sliced membership test.
    const int cls = lane >> 1;                      // class this lane counts
    const unsigned m0 = (cls & 1) ? 0xFFFFFFFFu : 0u;
    const unsigned m1 = (cls & 2) ? 0xFFFFFFFFu : 0u;
    const unsigned m2 = (cls & 4) ? 0xFFFFFFFFu : 0u;
    const unsigned m3 = (cls & 8) ? 0xFFFFFFFFu : 0u;
    const unsigned ginv = (lane & 1) ? 0u : 0xFFFFFFFFu;  // gmask = am ^ ginv

    unsigned cnt = 0;

    const int4* __restrict__ p4 = (const int4*)preds;
    const int4* __restrict__ a4 = (const int4*)attrs;

    const int gwarp  = blockIdx.x * WARPS_PER_BLOCK + warp;
    const int nwarps = gridDim.x * WARPS_PER_BLOCK;
    const int chunks = n4 >> 5;   // warp-sized int4 chunks (warp-uniform)

    // Main loop: 2 chunks per iteration, loads batched first (4x LDG.128).
    int c = gwarp;
    for (; c + nwarps < chunks; c += 2 * nwarps) {
        int ia = c * 32 + lane;
        int ib = (c + nwarps) * 32 + lane;
        int4 pa = p4[ia];
        int4 aa = a4[ia];
        int4 pb = p4[ib];
        int4 ab = a4[ib];

        ballot_round(pa.x, aa.x, m0, m1, m2, m3, ginv, cnt);
        ballot_round(pa.y, aa.y, m0, m1, m2, m3, ginv, cnt);
        ballot_round(pa.z, aa.z, m0, m1, m2, m3, ginv, cnt);
        ballot_round(pa.w, aa.w, m0, m1, m2, m3, ginv, cnt);
        ballot_round(pb.x, ab.x, m0, m1, m2, m3, ginv, cnt);
        ballot_round(pb.y, ab.y, m0, m1, m2, m3, ginv, cnt);
        ballot_round(pb.z, ab.z, m0, m1, m2, m3, ginv, cnt);
        ballot_round(pb.w, ab.w, m0, m1, m2, m3, ginv, cnt);
    }
    for (; c < chunks; c += nwarps) {
        int i = c * 32 + lane;
        int4 p = p4[i];
        int4 a = a4[i];
        ballot_round(p.x, a.x, m0, m1, m2, m3, ginv, cnt);
        ballot_round(p.y, a.y, m0, m1, m2, m3, ginv, cnt);
        ballot_round(p.z, a.z, m0, m1, m2, m3, ginv, cnt);
        ballot_round(p.w, a.w, m0, m1, m2, m3, ginv, cnt);
    }

    // Remainder: elements [chunks*128, n). Handled by block 0, warp 0 with
    // sentinel pred=15 (class 15 -> counted by lanes 30/31 only, discarded).
    if (blockIdx.x == 0 && warp == 0) {
        for (int base = chunks * 128; base < n; base += 32) {
            int i = base + lane;
            int p = (i < n) ? preds[i] : 15;
            int a = (i < n) ? attrs[i] : 0;
            ballot_round(p, a, m0, m1, m2, m3, ginv, cnt);
        }
    }

    // Per-warp counters -> shared
    if (lane < N_BINS) warp_cnt[warp][lane] = cnt;
    __syncthreads();

    // Block reduce (18 threads) -> global atomics
    if (threadIdx.x < N_BINS) {
        unsigned s = 0;
        #pragma unroll
        for (int w = 0; w < WARPS_PER_BLOCK; w++) s += warp_cnt[w][threadIdx.x];
        atomicAdd(&g_counts[threadIdx.x], s);
    }

    // Release + ticket: last block finalizes.
    __syncthreads();
    if (threadIdx.x == 0) {
        __threadfence();
        unsigned t = atomicAdd(&g_ticket, 1u);
        is_last = (t == gridDim.x - 1) ? 1u : 0u;
    }
    __syncthreads();

    if (is_last && threadIdx.x == 0) {
        __threadfence();  // acquire side
        float cb[N_BINS];
        #pragma unroll
        for (int b = 0; b < N_BINS; b++)
            cb[b] = (float)atomicAdd(&g_counts[b], 0u);  // coherent read

        float n1 = 0.0f;
        #pragma unroll
        for (int b = 0; b < N_CLASSES; b++) n1 += cb[2 * b + 1];
        float n0 = n_total - n1;

        float s = 0.0f;
        #pragma unroll
        for (int b = 0; b < N_CLASSES; b++) {
            float d = cb[2 * b] / n0 - cb[2 * b + 1] / n1;
            s += d * d;
        }
        out[0] = s;

        // Reset globals for the next graph replay.
        #pragma unroll
        for (int b = 0; b < N_BINS; b++)
            atomicExch(&g_counts[b], 0u);
        __threadfence();
        atomicExch(&g_ticket, 0u);
    }
}

extern "C" void kernel_launch(void* const* d_in, const int* in_sizes, int n_in,
                              void* d_out, int out_size)
{
    const int* preds = (const int*)d_in[0];
    const int* attrs = (const int*)d_in[1];
    float* out = (float*)d_out;
    int n  = in_sizes[0];
    int n4 = n >> 2;

    int blocks = ((n4 >> 5) + WARPS_PER_BLOCK - 1) / WARPS_PER_BLOCK;
    const int max_blocks = 148 * 8;
    if (blocks > max_blocks) blocks = max_blocks;
    if (blocks < 1) blocks = 1;

    spd_loss_kernel<<<blocks, THREADS_PER_BLOCK>>>(preds, attrs, out, n, n4, (float)n);
}

// round 4
// speedup vs baseline: 1.2695x; 1.1014x over previous
#include <cuda_runtime.h>
#include <cuda_bf16.h>

#define N_CLASSES 9
#define N_GROUPS  2
#define N_BINS    (N_CLASSES * N_GROUPS)   // 18
#define WARPS_PER_BLOCK 8
#define THREADS_PER_BLOCK (WARPS_PER_BLOCK * 32)

// Global scratch (no allocations allowed). Zero-initialized at load; the last
// block of every launch resets them, so every graph replay sees clean state.
__device__ unsigned int g_counts[N_BINS];
__device__ unsigned int g_ticket;

// Packed accumulate: 9 class-fields of 7 bits in a 64-bit register, one
// accumulator per attr value. ~9 instructions/element, IMAD on fma pipe.
__device__ __forceinline__ void acc_elem(int pred, int attr,
                                         unsigned long long& acc0,
                                         unsigned long long& acc1)
{
    unsigned s = (unsigned)pred * 7u;
    unsigned long long inc = 1ULL << s;
    if (attr) acc1 += inc; else acc0 += inc;   // predicated IADD3/IADD3.X
}

__device__ __forceinline__ void flush_accs(unsigned long long& acc0,
                                           unsigned long long& acc1,
                                           unsigned int* blk)
{
    #pragma unroll
    for (int c = 0; c < N_CLASSES; c++) {
        unsigned f0 = (unsigned)(acc0 >> (7 * c)) & 0x7Fu;
        unsigned f1 = (unsigned)(acc1 >> (7 * c)) & 0x7Fu;
        // Warp-uniform addresses -> ptxas REDUX-aggregates to one ATOMS each.
        atomicAdd(&blk[2 * c + 0], f0);
        atomicAdd(&blk[2 * c + 1], f1);
    }
    acc0 = 0ULL;
    acc1 = 0ULL;
}

__global__ void __launch_bounds__(THREADS_PER_BLOCK)
spd_loss_kernel(const int* __restrict__ preds,
                const int* __restrict__ attrs,
                float* __restrict__ out,
                int n, int n4, float n_total)
{
    __shared__ unsigned int blk[N_BINS];
    __shared__ unsigned int is_last;

    if (threadIdx.x < N_BINS) blk[threadIdx.x] = 0u;
    __syncthreads();

    unsigned long long acc0 = 0ULL, acc1 = 0ULL;

    const int4* __restrict__ p4 = (const int4*)preds;
    const int4* __restrict__ a4 = (const int4*)attrs;

    const int tid    = blockIdx.x * THREADS_PER_BLOCK + threadIdx.x;
    const int stride = gridDim.x * THREADS_PER_BLOCK;

    // Main loop: 2 int4 pairs per iteration (4 independent LDG.128 in flight).
    // Safety flush every 15 iterations (15*8 = 120 < 127 field capacity);
    // at this problem size each thread sees <= ~56 elements, so it never fires.
    int pending = 0;
    int i = tid;
    for (; i + stride < n4; i += 2 * stride) {
        int4 pa = p4[i];
        int4 aa = a4[i];
        int4 pb = p4[i + stride];
        int4 ab = a4[i + stride];

        acc_elem(pa.x, aa.x, acc0, acc1);
        acc_elem(pa.y, aa.y, acc0, acc1);
        acc_elem(pa.z, aa.z, acc0, acc1);
        acc_elem(pa.w, aa.w, acc0, acc1);
        acc_elem(pb.x, ab.x, acc0, acc1);
        acc_elem(pb.y, ab.y, acc0, acc1);
        acc_elem(pb.z, ab.z, acc0, acc1);
        acc_elem(pb.w, ab.w, acc0, acc1);

        if (++pending == 15) { flush_accs(acc0, acc1, blk); pending = 0; }
    }
    for (; i < n4; i += stride) {
        int4 p = p4[i];
        int4 a = a4[i];
        acc_elem(p.x, a.x, acc0, acc1);
        acc_elem(p.y, a.y, acc0, acc1);
        acc_elem(p.z, a.z, acc0, acc1);
        acc_elem(p.w, a.w, acc0, acc1);
    }

    // Scalar tail (n not multiple of 4) — block 0 only, tiny.
    if (blockIdx.x == 0) {
        for (int k = n4 * 4 + threadIdx.x; k < n; k += THREADS_PER_BLOCK)
            acc_elem(preds[k], attrs[k], acc0, acc1);
    }

    flush_accs(acc0, acc1, blk);
    __syncthreads();

    // Block totals -> global atomics
    if (threadIdx.x < N_BINS)
        atomicAdd(&g_counts[threadIdx.x], blk[threadIdx.x]);

    // Release + ticket: last block finalizes.
    __syncthreads();
    if (threadIdx.x == 0) {
        __threadfence();
        unsigned t = atomicAdd(&g_ticket, 1u);
        is_last = (t == gridDim.x - 1) ? 1u : 0u;
    }
    __syncthreads();

    if (is_last && threadIdx.x == 0) {
        __threadfence();  // acquire side
        float cb[N_BINS];
        #pragma unroll
        for (int b = 0; b < N_BINS; b++)
            cb[b] = (float)atomicAdd(&g_counts[b], 0u);  // coherent read

        float n1 = 0.0f;
        #pragma unroll
        for (int b = 0; b < N_CLASSES; b++) n1 += cb[2 * b + 1];
        float n0 = n_total - n1;

        float s = 0.0f;
        #pragma unroll
        for (int b = 0; b < N_CLASSES; b++) {
            float d = cb[2 * b] / n0 - cb[2 * b + 1] / n1;
            s += d * d;
        }
        out[0] = s;

        // Reset globals for the next graph replay.
        #pragma unroll
        for (int b = 0; b < N_BINS; b++)
            atomicExch(&g_counts[b], 0u);
        __threadfence();
        atomicExch(&g_ticket, 0u);
    }
}

extern "C" void kernel_launch(void* const* d_in, const int* in_sizes, int n_in,
                              void* d_out, int out_size)
{
    const int* preds = (const int*)d_in[0];
    const int* attrs = (const int*)d_in[1];
    float* out = (float*)d_out;
    int n  = in_sizes[0];
    int n4 = n >> 2;

    int blocks = (n4 + THREADS_PER_BLOCK - 1) / THREADS_PER_BLOCK;
    const int max_blocks = 148 * 8;
    if (blocks > max_blocks) blocks = max_blocks;
    if (blocks < 1) blocks = 1;

    spd_loss_kernel<<<blocks, THREADS_PER_BLOCK>>>(preds, attrs, out, n, n4, (float)n);
}

// round 5
// speedup vs baseline: 1.3482x; 1.0620x over previous
#include <cuda_runtime.h>
#include <cuda_bf16.h>

#define N_CLASSES 9
#define N_GROUPS  2
#define N_BINS    (N_CLASSES * N_GROUPS)   // 18
#define WARPS_PER_BLOCK 8
#define THREADS_PER_BLOCK (WARPS_PER_BLOCK * 32)
#define CTAS_PER_SM 6
#define NUM_SMS 148

// Global scratch (no allocations allowed). Zero-initialized at load; the last
// block of every launch resets them, so every graph replay sees clean state.
__device__ unsigned int g_counts[N_BINS];
__device__ unsigned int g_ticket;

// Packed accumulate: 9 class-fields of 7 bits in a 64-bit register, one
// accumulator per attr value.
__device__ __forceinline__ void acc_elem(int pred, int attr,
                                         unsigned long long& acc0,
                                         unsigned long long& acc1)
{
    unsigned s = (unsigned)pred * 7u;
    unsigned long long inc = 1ULL << s;
    if (attr) acc1 += inc; else acc0 += inc;   // predicated IADD3/IADD3.X
}

__device__ __forceinline__ void flush_pair(unsigned long long& acc0,
                                           unsigned long long& acc1,
                                           unsigned int* blk)
{
    #pragma unroll
    for (int c = 0; c < N_CLASSES; c++) {
        unsigned f0 = (unsigned)(acc0 >> (7 * c)) & 0x7Fu;
        unsigned f1 = (unsigned)(acc1 >> (7 * c)) & 0x7Fu;
        atomicAdd(&blk[2 * c + 0], f0);   // warp-uniform -> REDUX-aggregated
        atomicAdd(&blk[2 * c + 1], f1);
    }
    acc0 = 0ULL;
    acc1 = 0ULL;
}

__global__ void __launch_bounds__(THREADS_PER_BLOCK, CTAS_PER_SM)
spd_loss_kernel(const int* __restrict__ preds,
                const int* __restrict__ attrs,
                float* __restrict__ out,
                int n, int n4, float n_total)
{
    __shared__ unsigned int blk[N_BINS];
    __shared__ unsigned int is_last;

    if (threadIdx.x < N_BINS) blk[threadIdx.x] = 0u;
    __syncthreads();

    // Two independent accumulator pairs -> half-length dependency chains.
    unsigned long long a0 = 0ULL, a1 = 0ULL;   // pair A
    unsigned long long b0 = 0ULL, b1 = 0ULL;   // pair B

    const int4* __restrict__ p4 = (const int4*)preds;
    const int4* __restrict__ a4 = (const int4*)attrs;

    const int tid    = blockIdx.x * THREADS_PER_BLOCK + threadIdx.x;
    const int stride = gridDim.x * THREADS_PER_BLOCK;

    // Main loop: 2 int4 pairs per iteration, loads front-batched (4x LDG.128).
    // Safety flush every 25 iterations: 25*4 = 100 < 127 field capacity per
    // accumulator pair. At this problem size (~19 iters/thread) it never fires.
    int pending = 0;
    int i = tid;
    for (; i + stride < n4; i += 2 * stride) {
        int4 pa = p4[i];
        int4 aa = a4[i];
        int4 pb = p4[i + stride];
        int4 ab = a4[i + stride];

        acc_elem(pa.x, aa.x, a0, a1);
        acc_elem(pa.y, aa.y, a0, a1);
        acc_elem(pa.z, aa.z, a0, a1);
        acc_elem(pa.w, aa.w, a0, a1);
        acc_elem(pb.x, ab.x, b0, b1);
        acc_elem(pb.y, ab.y, b0, b1);
        acc_elem(pb.z, ab.z, b0, b1);
        acc_elem(pb.w, ab.w, b0, b1);

        if (++pending == 25) {
            flush_pair(a0, a1, blk);
            flush_pair(b0, b1, blk);
            pending = 0;
        }
    }
    for (; i < n4; i += stride) {
        int4 p = p4[i];
        int4 a = a4[i];
        acc_elem(p.x, a.x, a0, a1);
        acc_elem(p.y, a.y, a0, a1);
        acc_elem(p.z, a.z, a0, a1);
        acc_elem(p.w, a.w, a0, a1);
    }

    // Scalar tail (n not multiple of 4) — block 0 only, tiny.
    if (blockIdx.x == 0) {
        for (int k = n4 * 4 + threadIdx.x; k < n; k += THREADS_PER_BLOCK)
            acc_elem(preds[k], attrs[k], b0, b1);
    }

    flush_pair(a0, a1, blk);
    flush_pair(b0, b1, blk);
    __syncthreads();

    // Block totals -> global atomics
    if (threadIdx.x < N_BINS)
        atomicAdd(&g_counts[threadIdx.x], blk[threadIdx.x]);

    // Release + ticket: last block finalizes.
    __syncthreads();
    if (threadIdx.x == 0) {
        __threadfence();
        unsigned t = atomicAdd(&g_ticket, 1u);
        is_last = (t == gridDim.x - 1) ? 1u : 0u;
    }
    __syncthreads();

    if (is_last && threadIdx.x == 0) {
        __threadfence();  // acquire side
        float cb[N_BINS];
        #pragma unroll
        for (int b = 0; b < N_BINS; b++)
            cb[b] = (float)atomicAdd(&g_counts[b], 0u);  // coherent read

        float n1 = 0.0f;
        #pragma unroll
        for (int c = 0; c < N_CLASSES; c++) n1 += cb[2 * c + 1];
        float n0 = n_total - n1;

        float s = 0.0f;
        #pragma unroll
        for (int c = 0; c < N_CLASSES; c++) {
            float d = cb[2 * c] / n0 - cb[2 * c + 1] / n1;
            s += d * d;
        }
        out[0] = s;

        // Reset globals for the next graph replay.
        #pragma unroll
        for (int c = 0; c < N_BINS; c++)
            atomicExch(&g_counts[c], 0u);
        __threadfence();
        atomicExch(&g_ticket, 0u);
    }
}

extern "C" void kernel_launch(void* const* d_in, const int* in_sizes, int n_in,
                              void* d_out, int out_size)
{
    const int* preds = (const int*)d_in[0];
    const int* attrs = (const int*)d_in[1];
    float* out = (float*)d_out;
    int n  = in_sizes[0];
    int n4 = n >> 2;

    // Exactly ONE full wave: 148 SMs x 6 CTAs/SM (enforced by launch_bounds).
    int blocks = NUM_SMS * CTAS_PER_SM;   // 888
    int max_needed = (n4 + THREADS_PER_BLOCK - 1) / THREADS_PER_BLOCK;
    if (blocks > max_needed) blocks = max_needed;
    if (blocks < 1) blocks = 1;

    spd_loss_kernel<<<blocks, THREADS_PER_BLOCK>>>(preds, attrs, out, n, n4, (float)n);
}